// round 2
// baseline (speedup 1.0000x reference)
#include <cuda_runtime.h>
#include <math.h>

// ---------------- problem constants ----------------
#define N_EMBD   2048
#define N_HEAD   16
#define HEAD_DIM 128
#define N_INNER  8192
#define SEQ      2048
#define BATCH    2
#define ROWS     (BATCH*SEQ)     /* 4096 */
#define QKV_W    (3*N_EMBD)      /* 6144 */

// ---------------- scratch (device globals; no allocs allowed) ----------------
__device__ float g_ln   [(size_t)ROWS * N_EMBD];
__device__ float g_qkv  [(size_t)ROWS * QKV_W];
__device__ float g_attn [(size_t)ROWS * N_EMBD];
__device__ float g_hid  [(size_t)ROWS * N_EMBD];
__device__ float g_fc   [(size_t)ROWS * N_INNER];
__device__ float g_sA   [N_EMBD];
__device__ float g_sM   [N_INNER];

// ======================= LayerNorm: one block per row =======================
__global__ __launch_bounds__(256) void ln_kernel(const float* __restrict__ x,
                                                 const float* __restrict__ g,
                                                 const float* __restrict__ b,
                                                 float* __restrict__ y) {
    __shared__ float red[8];
    __shared__ float s_mean, s_rstd;
    const int row = blockIdx.x, tid = threadIdx.x;
    const float* xr = x + (size_t)row * N_EMBD;
    float v[8];
    float s = 0.f;
#pragma unroll
    for (int k = 0; k < 8; k++) { v[k] = xr[tid + k * 256]; s += v[k]; }
#pragma unroll
    for (int o = 16; o > 0; o >>= 1) s += __shfl_xor_sync(0xffffffffu, s, o);
    if ((tid & 31) == 0) red[tid >> 5] = s;
    __syncthreads();
    if (tid == 0) {
        float t = 0.f;
#pragma unroll
        for (int i = 0; i < 8; i++) t += red[i];
        s_mean = t * (1.f / N_EMBD);
    }
    __syncthreads();
    const float mu = s_mean;
    float vs = 0.f;
#pragma unroll
    for (int k = 0; k < 8; k++) { float d = v[k] - mu; vs += d * d; }
#pragma unroll
    for (int o = 16; o > 0; o >>= 1) vs += __shfl_xor_sync(0xffffffffu, vs, o);
    if ((tid & 31) == 0) red[tid >> 5] = vs;
    __syncthreads();
    if (tid == 0) {
        float t = 0.f;
#pragma unroll
        for (int i = 0; i < 8; i++) t += red[i];
        s_rstd = rsqrtf(t * (1.f / N_EMBD) + 1e-5f);
    }
    __syncthreads();
    const float rstd = s_rstd;
    float* yr = y + (size_t)row * N_EMBD;
#pragma unroll
    for (int k = 0; k < 8; k++) {
        const int c = tid + k * 256;
        yr[c] = (v[k] - mu) * rstd * g[c] + b[c];
    }
}

// ========== weight-norm column scales: s[j] = g[j] / ||v[:,j]||_2 ==========
// v is [rows, cols] row-major; norm over axis 0. Block handles 32 columns.
__global__ __launch_bounds__(256) void colnorm_kernel(const float* __restrict__ v,
                                                      const float* __restrict__ g,
                                                      float* __restrict__ scale,
                                                      int rows, int cols) {
    __shared__ float red[8][32];
    const int lane = threadIdx.x & 31;
    const int r0   = threadIdx.x >> 5;           // 0..7
    const int j    = blockIdx.x * 32 + lane;
    float acc = 0.f;
    for (int r = r0; r < rows; r += 8) {
        float t = v[(size_t)r * cols + j];
        acc += t * t;
    }
    red[r0][lane] = acc;
    __syncthreads();
    if (r0 == 0) {
        float s = red[0][lane];
#pragma unroll
        for (int q = 1; q < 8; q++) s += red[q][lane];
        scale[j] = g[j] / sqrtf(s);
    }
}

// ======================= SGEMM: C[M,N] = A[M,K] @ B[N,K]^T + epilogue =======
// A row-major [M,K]; B row-major [N,K] (K contiguous for both).
// Epilogue: +bias[col]; optional exact GELU; optional +res[row,col].
// Optional per-K column scale on A (weight-norm fold).
template<bool COLSCALE, bool DOGELU, bool RES>
__global__ __launch_bounds__(256) void sgemm_nt(const float* __restrict__ A,
                                                const float* __restrict__ B,
                                                const float* __restrict__ bias,
                                                const float* __restrict__ cs,
                                                const float* __restrict__ res,
                                                float* __restrict__ C,
                                                int M, int N, int K) {
    __shared__ float As[16][132];
    __shared__ float Bs[16][132];
    const int tid = threadIdx.x;
    const int m0 = blockIdx.y * 128;
    const int n0 = blockIdx.x * 128;
    const int tr = tid >> 4;       // 0..15 -> rows tr*8..tr*8+7
    const int tc = tid & 15;       // 0..15 -> cols tc*8..tc*8+7

    float acc[8][8];
#pragma unroll
    for (int i = 0; i < 8; i++)
#pragma unroll
        for (int j = 0; j < 8; j++) acc[i][j] = 0.f;

    for (int k0 = 0; k0 < K; k0 += 16) {
#pragma unroll
        for (int q = 0; q < 2; q++) {
            const int idx = tid + q * 256;          // 0..511
            const int r  = idx >> 2;                // 0..127
            const int kk = (idx & 3) * 4;           // 0,4,8,12
            float4 av = *(const float4*)&A[(size_t)(m0 + r) * K + k0 + kk];
            if (COLSCALE) {
                av.x *= cs[k0 + kk + 0];
                av.y *= cs[k0 + kk + 1];
                av.z *= cs[k0 + kk + 2];
                av.w *= cs[k0 + kk + 3];
            }
            As[kk + 0][r] = av.x; As[kk + 1][r] = av.y;
            As[kk + 2][r] = av.z; As[kk + 3][r] = av.w;
            float4 bv = *(const float4*)&B[(size_t)(n0 + r) * K + k0 + kk];
            Bs[kk + 0][r] = bv.x; Bs[kk + 1][r] = bv.y;
            Bs[kk + 2][r] = bv.z; Bs[kk + 3][r] = bv.w;
        }
        __syncthreads();
#pragma unroll
        for (int kk = 0; kk < 16; kk++) {
            float a[8], bb[8];
            *(float4*)&a[0]  = *(const float4*)&As[kk][tr * 8];
            *(float4*)&a[4]  = *(const float4*)&As[kk][tr * 8 + 4];
            *(float4*)&bb[0] = *(const float4*)&Bs[kk][tc * 8];
            *(float4*)&bb[4] = *(const float4*)&Bs[kk][tc * 8 + 4];
#pragma unroll
            for (int i = 0; i < 8; i++)
#pragma unroll
                for (int j = 0; j < 8; j++) acc[i][j] += a[i] * bb[j];
        }
        __syncthreads();
    }

#pragma unroll
    for (int i = 0; i < 8; i++) {
        const int row = m0 + tr * 8 + i;
#pragma unroll
        for (int j0 = 0; j0 < 8; j0 += 4) {
            const int col = n0 + tc * 8 + j0;
            float4 cv;
            cv.x = acc[i][j0 + 0]; cv.y = acc[i][j0 + 1];
            cv.z = acc[i][j0 + 2]; cv.w = acc[i][j0 + 3];
            const float4 bi = *(const float4*)&bias[col];
            cv.x += bi.x; cv.y += bi.y; cv.z += bi.z; cv.w += bi.w;
            if (DOGELU) {
                cv.x = 0.5f * cv.x * (1.f + erff(cv.x * 0.70710678118654752f));
                cv.y = 0.5f * cv.y * (1.f + erff(cv.y * 0.70710678118654752f));
                cv.z = 0.5f * cv.z * (1.f + erff(cv.z * 0.70710678118654752f));
                cv.w = 0.5f * cv.w * (1.f + erff(cv.w * 0.70710678118654752f));
            }
            if (RES) {
                const float4 rv = *(const float4*)&res[(size_t)row * N + col];
                cv.x += rv.x; cv.y += rv.y; cv.z += rv.z; cv.w += rv.w;
            }
            *(float4*)&C[(size_t)row * N + col] = cv;
        }
    }
}

// ======================= Flash attention (fp32, online softmax) ============
// Grid: (SEQ/64, H, B). Block: 256 threads. 64 queries x full D=128 per CTA.
// q/k/v live interleaved in qkv buffer: row stride 6144; k at +2048, v at +4096.
// emotion_bias is constant over the softmax axis -> dropped (softmax invariant).
#define ATT_SMEM_FLOATS (128*72*2 + 64*128 + 64*68 + 3*64)

__global__ __launch_bounds__(256) void attn_kernel(const float* __restrict__ qkv,
                                                   float* __restrict__ out) {
    extern __shared__ float sm[];
    float* Qt   = sm;                   // [128][72]  (d-major, row index last)
    float* Kt   = Qt + 128 * 72;        // [128][72]
    float* Vs   = Kt + 128 * 72;        // [64][128]
    float* Ss   = Vs + 64 * 128;        // [64][68]
    float* mrow = Ss + 64 * 68;
    float* lrow = mrow + 64;
    float* crow = lrow + 64;

    const int tid = threadIdx.x;
    const int qb  = blockIdx.x * 64;
    const int h   = blockIdx.y;
    const int b   = blockIdx.z;
    const size_t rs = QKV_W;
    const float* qbase = qkv + (size_t)b * SEQ * rs + (size_t)h * HEAD_DIM;
    const float* kbase = qbase + N_EMBD;
    const float* vbase = qbase + 2 * N_EMBD;

    // load Q transposed: Qt[d][r]
#pragma unroll
    for (int q = 0; q < 8; q++) {
        const int idx = tid + q * 256;         // 0..2047
        const int r  = idx >> 5;               // 0..63
        const int d4 = (idx & 31) * 4;         // 0..124
        const float4 v = *(const float4*)&qbase[(size_t)(qb + r) * rs + d4];
        Qt[(d4 + 0) * 72 + r] = v.x; Qt[(d4 + 1) * 72 + r] = v.y;
        Qt[(d4 + 2) * 72 + r] = v.z; Qt[(d4 + 3) * 72 + r] = v.w;
    }
    if (tid < 64) { mrow[tid] = -INFINITY; lrow[tid] = 0.f; }

    const int tr = tid >> 4;   // 0..15
    const int tc = tid & 15;   // 0..15
    float o[4][8];
#pragma unroll
    for (int i = 0; i < 4; i++)
#pragma unroll
        for (int j = 0; j < 8; j++) o[i][j] = 0.f;

    __syncthreads();

    for (int kt = 0; kt < SEQ; kt += 64) {
        // load K transposed + V
#pragma unroll
        for (int q = 0; q < 8; q++) {
            const int idx = tid + q * 256;
            const int r  = idx >> 5;
            const int d4 = (idx & 31) * 4;
            const float4 kv = *(const float4*)&kbase[(size_t)(kt + r) * rs + d4];
            Kt[(d4 + 0) * 72 + r] = kv.x; Kt[(d4 + 1) * 72 + r] = kv.y;
            Kt[(d4 + 2) * 72 + r] = kv.z; Kt[(d4 + 3) * 72 + r] = kv.w;
            const float4 vv = *(const float4*)&vbase[(size_t)(kt + r) * rs + d4];
            *(float4*)&Vs[r * 128 + d4] = vv;
        }
        __syncthreads();

        // S = Q K^T / sqrt(D)
        float s[4][4];
#pragma unroll
        for (int i = 0; i < 4; i++)
#pragma unroll
            for (int j = 0; j < 4; j++) s[i][j] = 0.f;
#pragma unroll 8
        for (int kk = 0; kk < 128; kk++) {
            float a[4], bv[4];
            *(float4*)a  = *(const float4*)&Qt[kk * 72 + tr * 4];
            *(float4*)bv = *(const float4*)&Kt[kk * 72 + tc * 4];
#pragma unroll
            for (int i = 0; i < 4; i++)
#pragma unroll
                for (int j = 0; j < 4; j++) s[i][j] += a[i] * bv[j];
        }
        const float sc = 0.08838834764831845f;  // 1/sqrt(128)
#pragma unroll
        for (int i = 0; i < 4; i++)
#pragma unroll
            for (int j = 0; j < 4; j++)
                Ss[(tr * 4 + i) * 68 + tc * 4 + j] = s[i][j] * sc;
        __syncthreads();

        // online softmax stats, one thread per row
        if (tid < 64) {
            float* srow = &Ss[tid * 68];
            const float mold = mrow[tid];
            float mn = mold;
#pragma unroll 8
            for (int c = 0; c < 64; c++) mn = fmaxf(mn, srow[c]);
            const float corr = expf(mold - mn);   // 0 on first tile
            float sum = 0.f;
#pragma unroll 8
            for (int c = 0; c < 64; c++) {
                const float p = expf(srow[c] - mn);
                srow[c] = p;
                sum += p;
            }
            lrow[tid] = lrow[tid] * corr + sum;
            mrow[tid] = mn;
            crow[tid] = corr;
        }
        __syncthreads();

        // O = O*corr + P @ V
#pragma unroll
        for (int i = 0; i < 4; i++) {
            const float cf = crow[tr * 4 + i];
#pragma unroll
            for (int j = 0; j < 8; j++) o[i][j] *= cf;
        }
#pragma unroll 4
        for (int k = 0; k < 64; k++) {
            float p[4];
#pragma unroll
            for (int i = 0; i < 4; i++) p[i] = Ss[(tr * 4 + i) * 68 + k];
            float v0[4], v1[4];
            *(float4*)v0 = *(const float4*)&Vs[k * 128 + tc * 4];
            *(float4*)v1 = *(const float4*)&Vs[k * 128 + 64 + tc * 4];
#pragma unroll
            for (int i = 0; i < 4; i++) {
#pragma unroll
                for (int j = 0; j < 4; j++) {
                    o[i][j]     += p[i] * v0[j];
                    o[i][4 + j] += p[i] * v1[j];
                }
            }
        }
        __syncthreads();
    }

    // normalize + write attn output in [B,S,E] layout (e = h*128 + d)
#pragma unroll
    for (int i = 0; i < 4; i++) {
        const int r = qb + tr * 4 + i;
        const float inv = 1.f / lrow[tr * 4 + i];
        const size_t base = ((size_t)b * SEQ + r) * N_EMBD + (size_t)h * HEAD_DIM;
        float4 r0, r1;
        r0.x = o[i][0] * inv; r0.y = o[i][1] * inv; r0.z = o[i][2] * inv; r0.w = o[i][3] * inv;
        r1.x = o[i][4] * inv; r1.y = o[i][5] * inv; r1.z = o[i][6] * inv; r1.w = o[i][7] * inv;
        *(float4*)&out[base + tc * 4]      = r0;
        *(float4*)&out[base + 64 + tc * 4] = r1;
    }
}

// =========================== launch sequence ===============================
extern "C" void kernel_launch(void* const* d_in, const int* in_sizes, int n_in,
                              void* d_out, int out_size) {
    const float* hs      = (const float*)d_in[0];
    const float* ln1_g   = (const float*)d_in[1];
    const float* ln1_b   = (const float*)d_in[2];
    const float* w_qkv   = (const float*)d_in[3];
    const float* b_qkv   = (const float*)d_in[4];
    const float* attn_v  = (const float*)d_in[5];
    const float* attn_g  = (const float*)d_in[6];
    const float* attn_b  = (const float*)d_in[7];
    /* d_in[8] = emotion_bias: softmax-invariant, unused */
    const float* ln2_g   = (const float*)d_in[9];
    const float* ln2_b   = (const float*)d_in[10];
    const float* w_fc    = (const float*)d_in[11];
    const float* b_fc    = (const float*)d_in[12];
    const float* mlp_v   = (const float*)d_in[13];
    const float* mlp_g   = (const float*)d_in[14];
    const float* mlp_b   = (const float*)d_in[15];
    float* out = (float*)d_out;

    float *ln, *qkv, *attn, *hid, *fc, *sA, *sM;
    cudaGetSymbolAddress((void**)&ln,   g_ln);
    cudaGetSymbolAddress((void**)&qkv,  g_qkv);
    cudaGetSymbolAddress((void**)&attn, g_attn);
    cudaGetSymbolAddress((void**)&hid,  g_hid);
    cudaGetSymbolAddress((void**)&fc,   g_fc);
    cudaGetSymbolAddress((void**)&sA,   g_sA);
    cudaGetSymbolAddress((void**)&sM,   g_sM);

    const size_t att_smem = (size_t)ATT_SMEM_FLOATS * sizeof(float);
    cudaFuncSetAttribute(attn_kernel,
                         cudaFuncAttributeMaxDynamicSharedMemorySize,
                         (int)att_smem);

    // weight-norm column scales
    colnorm_kernel<<<N_EMBD / 32, 256>>>(attn_v, attn_g, sA, N_EMBD, N_EMBD);
    colnorm_kernel<<<N_INNER / 32, 256>>>(mlp_v, mlp_g, sM, N_EMBD, N_INNER);

    // LN1
    ln_kernel<<<ROWS, 256>>>(hs, ln1_g, ln1_b, ln);

    // QKV: [4096,6144] = ln @ w_qkv^T + b_qkv
    sgemm_nt<false, false, false><<<dim3(QKV_W / 128, ROWS / 128), 256>>>(
        ln, w_qkv, b_qkv, nullptr, nullptr, qkv, ROWS, QKV_W, N_EMBD);

    // attention
    attn_kernel<<<dim3(SEQ / 64, N_HEAD, BATCH), 256, att_smem>>>(qkv, attn);

    // attn proj (weight-norm folded) + residual -> hidden
    sgemm_nt<true, false, true><<<dim3(N_EMBD / 128, ROWS / 128), 256>>>(
        attn, attn_v, attn_b, sA, hs, hid, ROWS, N_EMBD, N_EMBD);

    // LN2
    ln_kernel<<<ROWS, 256>>>(hid, ln2_g, ln2_b, ln);

    // FC + exact GELU: [4096,8192]
    sgemm_nt<false, true, false><<<dim3(N_INNER / 128, ROWS / 128), 256>>>(
        ln, w_fc, b_fc, nullptr, nullptr, fc, ROWS, N_INNER, N_EMBD);

    // MLP proj (weight-norm folded) + residual -> output
    sgemm_nt<true, false, true><<<dim3(N_EMBD / 128, ROWS / 128), 256>>>(
        fc, mlp_v, mlp_b, sM, hid, out, ROWS, N_EMBD, N_INNER);
}

// round 3
// speedup vs baseline: 1.0009x; 1.0009x over previous
#include <cuda_runtime.h>
#include <math.h>

// ---------------- problem constants ----------------
#define N_EMBD   2048
#define N_HEAD   16
#define HEAD_DIM 128
#define N_INNER  8192
#define SEQ      2048
#define BATCH    2
#define ROWS     (BATCH*SEQ)     /* 4096 */
#define QKV_W    (3*N_EMBD)      /* 6144 */

// ---------------- scratch (device globals; no allocs allowed) ----------------
__device__ float g_ln   [(size_t)ROWS * N_EMBD];
__device__ float g_qkv  [(size_t)ROWS * QKV_W];
__device__ float g_attn [(size_t)ROWS * N_EMBD];
__device__ float g_hid  [(size_t)ROWS * N_EMBD];
__device__ float g_fc   [(size_t)ROWS * N_INNER];
__device__ float g_sA   [N_EMBD];
__device__ float g_sM   [N_INNER];

// ======================= LayerNorm: one block per row =======================
__global__ __launch_bounds__(256) void ln_kernel(const float* __restrict__ x,
                                                 const float* __restrict__ g,
                                                 const float* __restrict__ b,
                                                 float* __restrict__ y) {
    __shared__ float red[8];
    __shared__ float s_mean, s_rstd;
    const int row = blockIdx.x, tid = threadIdx.x;
    const float* xr = x + (size_t)row * N_EMBD;
    float v[8];
    float s = 0.f;
#pragma unroll
    for (int k = 0; k < 8; k++) { v[k] = xr[tid + k * 256]; s += v[k]; }
#pragma unroll
    for (int o = 16; o > 0; o >>= 1) s += __shfl_xor_sync(0xffffffffu, s, o);
    if ((tid & 31) == 0) red[tid >> 5] = s;
    __syncthreads();
    if (tid == 0) {
        float t = 0.f;
#pragma unroll
        for (int i = 0; i < 8; i++) t += red[i];
        s_mean = t * (1.f / N_EMBD);
    }
    __syncthreads();
    const float mu = s_mean;
    float vs = 0.f;
#pragma unroll
    for (int k = 0; k < 8; k++) { float d = v[k] - mu; vs += d * d; }
#pragma unroll
    for (int o = 16; o > 0; o >>= 1) vs += __shfl_xor_sync(0xffffffffu, vs, o);
    if ((tid & 31) == 0) red[tid >> 5] = vs;
    __syncthreads();
    if (tid == 0) {
        float t = 0.f;
#pragma unroll
        for (int i = 0; i < 8; i++) t += red[i];
        s_rstd = rsqrtf(t * (1.f / N_EMBD) + 1e-5f);
    }
    __syncthreads();
    const float rstd = s_rstd;
    float* yr = y + (size_t)row * N_EMBD;
#pragma unroll
    for (int k = 0; k < 8; k++) {
        const int c = tid + k * 256;
        yr[c] = (v[k] - mu) * rstd * g[c] + b[c];
    }
}

// ========== weight-norm column scales: s[j] = g[j] / ||v[:,j]||_2 ==========
// v is [rows, cols] row-major; norm over axis 0. Block handles 32 columns.
__global__ __launch_bounds__(256) void colnorm_kernel(const float* __restrict__ v,
                                                      const float* __restrict__ g,
                                                      float* __restrict__ scale,
                                                      int rows, int cols) {
    __shared__ float red[8][32];
    const int lane = threadIdx.x & 31;
    const int r0   = threadIdx.x >> 5;           // 0..7
    const int j    = blockIdx.x * 32 + lane;
    float acc = 0.f;
    for (int r = r0; r < rows; r += 8) {
        float t = v[(size_t)r * cols + j];
        acc += t * t;
    }
    red[r0][lane] = acc;
    __syncthreads();
    if (r0 == 0) {
        float s = red[0][lane];
#pragma unroll
        for (int q = 1; q < 8; q++) s += red[q][lane];
        scale[j] = g[j] / sqrtf(s);
    }
}

// ======================= SGEMM: C[M,N] = A[M,K] @ B[N,K]^T + epilogue =======
// A row-major [M,K]; B row-major [N,K] (K contiguous for both).
// Epilogue: +bias[col]; optional exact GELU; optional +res[row,col].
// Optional per-K column scale on A (weight-norm fold).
template<bool COLSCALE, bool DOGELU, bool RES>
__global__ __launch_bounds__(256) void sgemm_nt(const float* __restrict__ A,
                                                const float* __restrict__ B,
                                                const float* __restrict__ bias,
                                                const float* __restrict__ cs,
                                                const float* __restrict__ res,
                                                float* __restrict__ C,
                                                int M, int N, int K) {
    __shared__ float As[16][132];
    __shared__ float Bs[16][132];
    const int tid = threadIdx.x;
    const int m0 = blockIdx.y * 128;
    const int n0 = blockIdx.x * 128;
    const int tr = tid >> 4;       // 0..15 -> rows tr*8..tr*8+7
    const int tc = tid & 15;       // 0..15 -> cols tc*8..tc*8+7

    float acc[8][8];
#pragma unroll
    for (int i = 0; i < 8; i++)
#pragma unroll
        for (int j = 0; j < 8; j++) acc[i][j] = 0.f;

    for (int k0 = 0; k0 < K; k0 += 16) {
#pragma unroll
        for (int q = 0; q < 2; q++) {
            const int idx = tid + q * 256;          // 0..511
            const int r  = idx >> 2;                // 0..127
            const int kk = (idx & 3) * 4;           // 0,4,8,12
            float4 av = *(const float4*)&A[(size_t)(m0 + r) * K + k0 + kk];
            if (COLSCALE) {
                av.x *= cs[k0 + kk + 0];
                av.y *= cs[k0 + kk + 1];
                av.z *= cs[k0 + kk + 2];
                av.w *= cs[k0 + kk + 3];
            }
            As[kk + 0][r] = av.x; As[kk + 1][r] = av.y;
            As[kk + 2][r] = av.z; As[kk + 3][r] = av.w;
            float4 bv = *(const float4*)&B[(size_t)(n0 + r) * K + k0 + kk];
            Bs[kk + 0][r] = bv.x; Bs[kk + 1][r] = bv.y;
            Bs[kk + 2][r] = bv.z; Bs[kk + 3][r] = bv.w;
        }
        __syncthreads();
#pragma unroll
        for (int kk = 0; kk < 16; kk++) {
            float a[8], bb[8];
            *(float4*)&a[0]  = *(const float4*)&As[kk][tr * 8];
            *(float4*)&a[4]  = *(const float4*)&As[kk][tr * 8 + 4];
            *(float4*)&bb[0] = *(const float4*)&Bs[kk][tc * 8];
            *(float4*)&bb[4] = *(const float4*)&Bs[kk][tc * 8 + 4];
#pragma unroll
            for (int i = 0; i < 8; i++)
#pragma unroll
                for (int j = 0; j < 8; j++) acc[i][j] += a[i] * bb[j];
        }
        __syncthreads();
    }

#pragma unroll
    for (int i = 0; i < 8; i++) {
        const int row = m0 + tr * 8 + i;
#pragma unroll
        for (int j0 = 0; j0 < 8; j0 += 4) {
            const int col = n0 + tc * 8 + j0;
            float4 cv;
            cv.x = acc[i][j0 + 0]; cv.y = acc[i][j0 + 1];
            cv.z = acc[i][j0 + 2]; cv.w = acc[i][j0 + 3];
            const float4 bi = *(const float4*)&bias[col];
            cv.x += bi.x; cv.y += bi.y; cv.z += bi.z; cv.w += bi.w;
            if (DOGELU) {
                cv.x = 0.5f * cv.x * (1.f + erff(cv.x * 0.70710678118654752f));
                cv.y = 0.5f * cv.y * (1.f + erff(cv.y * 0.70710678118654752f));
                cv.z = 0.5f * cv.z * (1.f + erff(cv.z * 0.70710678118654752f));
                cv.w = 0.5f * cv.w * (1.f + erff(cv.w * 0.70710678118654752f));
            }
            if (RES) {
                const float4 rv = *(const float4*)&res[(size_t)row * N + col];
                cv.x += rv.x; cv.y += rv.y; cv.z += rv.z; cv.w += rv.w;
            }
            *(float4*)&C[(size_t)row * N + col] = cv;
        }
    }
}

// ======================= Flash attention (fp32, online softmax) ============
// Grid: (SEQ/64, H, B). Block: 256 threads. 64 queries x full D=128 per CTA.
// q/k/v live interleaved in qkv buffer: row stride 6144; k at +2048, v at +4096.
// emotion_bias is constant over the softmax axis -> dropped (softmax invariant).
#define ATT_SMEM_FLOATS (128*72*2 + 64*128 + 64*68 + 3*64)

__global__ __launch_bounds__(256) void attn_kernel(const float* __restrict__ qkv,
                                                   float* __restrict__ out) {
    extern __shared__ float sm[];
    float* Qt   = sm;                   // [128][72]  (d-major, row index last)
    float* Kt   = Qt + 128 * 72;        // [128][72]
    float* Vs   = Kt + 128 * 72;        // [64][128]
    float* Ss   = Vs + 64 * 128;        // [64][68]
    float* mrow = Ss + 64 * 68;
    float* lrow = mrow + 64;
    float* crow = lrow + 64;

    const int tid = threadIdx.x;
    const int qb  = blockIdx.x * 64;
    const int h   = blockIdx.y;
    const int b   = blockIdx.z;
    const size_t rs = QKV_W;
    const float* qbase = qkv + (size_t)b * SEQ * rs + (size_t)h * HEAD_DIM;
    const float* kbase = qbase + N_EMBD;
    const float* vbase = qbase + 2 * N_EMBD;

    // load Q transposed: Qt[d][r]
#pragma unroll
    for (int q = 0; q < 8; q++) {
        const int idx = tid + q * 256;         // 0..2047
        const int r  = idx >> 5;               // 0..63
        const int d4 = (idx & 31) * 4;         // 0..124
        const float4 v = *(const float4*)&qbase[(size_t)(qb + r) * rs + d4];
        Qt[(d4 + 0) * 72 + r] = v.x; Qt[(d4 + 1) * 72 + r] = v.y;
        Qt[(d4 + 2) * 72 + r] = v.z; Qt[(d4 + 3) * 72 + r] = v.w;
    }
    if (tid < 64) { mrow[tid] = -INFINITY; lrow[tid] = 0.f; }

    const int tr = tid >> 4;   // 0..15
    const int tc = tid & 15;   // 0..15
    float o[4][8];
#pragma unroll
    for (int i = 0; i < 4; i++)
#pragma unroll
        for (int j = 0; j < 8; j++) o[i][j] = 0.f;

    __syncthreads();

    for (int kt = 0; kt < SEQ; kt += 64) {
        // load K transposed + V
#pragma unroll
        for (int q = 0; q < 8; q++) {
            const int idx = tid + q * 256;
            const int r  = idx >> 5;
            const int d4 = (idx & 31) * 4;
            const float4 kv = *(const float4*)&kbase[(size_t)(kt + r) * rs + d4];
            Kt[(d4 + 0) * 72 + r] = kv.x; Kt[(d4 + 1) * 72 + r] = kv.y;
            Kt[(d4 + 2) * 72 + r] = kv.z; Kt[(d4 + 3) * 72 + r] = kv.w;
            const float4 vv = *(const float4*)&vbase[(size_t)(kt + r) * rs + d4];
            *(float4*)&Vs[r * 128 + d4] = vv;
        }
        __syncthreads();

        // S = Q K^T / sqrt(D)
        float s[4][4];
#pragma unroll
        for (int i = 0; i < 4; i++)
#pragma unroll
            for (int j = 0; j < 4; j++) s[i][j] = 0.f;
#pragma unroll 8
        for (int kk = 0; kk < 128; kk++) {
            float a[4], bv[4];
            *(float4*)a  = *(const float4*)&Qt[kk * 72 + tr * 4];
            *(float4*)bv = *(const float4*)&Kt[kk * 72 + tc * 4];
#pragma unroll
            for (int i = 0; i < 4; i++)
#pragma unroll
                for (int j = 0; j < 4; j++) s[i][j] += a[i] * bv[j];
        }
        const float sc = 0.08838834764831845f;  // 1/sqrt(128)
#pragma unroll
        for (int i = 0; i < 4; i++)
#pragma unroll
            for (int j = 0; j < 4; j++)
                Ss[(tr * 4 + i) * 68 + tc * 4 + j] = s[i][j] * sc;
        __syncthreads();

        // online softmax stats, one thread per row
        if (tid < 64) {
            float* srow = &Ss[tid * 68];
            const float mold = mrow[tid];
            float mn = mold;
#pragma unroll 8
            for (int c = 0; c < 64; c++) mn = fmaxf(mn, srow[c]);
            const float corr = expf(mold - mn);   // 0 on first tile
            float sum = 0.f;
#pragma unroll 8
            for (int c = 0; c < 64; c++) {
                const float p = expf(srow[c] - mn);
                srow[c] = p;
                sum += p;
            }
            lrow[tid] = lrow[tid] * corr + sum;
            mrow[tid] = mn;
            crow[tid] = corr;
        }
        __syncthreads();

        // O = O*corr + P @ V
#pragma unroll
        for (int i = 0; i < 4; i++) {
            const float cf = crow[tr * 4 + i];
#pragma unroll
            for (int j = 0; j < 8; j++) o[i][j] *= cf;
        }
#pragma unroll 4
        for (int k = 0; k < 64; k++) {
            float p[4];
#pragma unroll
            for (int i = 0; i < 4; i++) p[i] = Ss[(tr * 4 + i) * 68 + k];
            float v0[4], v1[4];
            *(float4*)v0 = *(const float4*)&Vs[k * 128 + tc * 4];
            *(float4*)v1 = *(const float4*)&Vs[k * 128 + 64 + tc * 4];
#pragma unroll
            for (int i = 0; i < 4; i++) {
#pragma unroll
                for (int j = 0; j < 4; j++) {
                    o[i][j]     += p[i] * v0[j];
                    o[i][4 + j] += p[i] * v1[j];
                }
            }
        }
        __syncthreads();
    }

    // normalize + write attn output in [B,S,E] layout (e = h*128 + d)
#pragma unroll
    for (int i = 0; i < 4; i++) {
        const int r = qb + tr * 4 + i;
        const float inv = 1.f / lrow[tr * 4 + i];
        const size_t base = ((size_t)b * SEQ + r) * N_EMBD + (size_t)h * HEAD_DIM;
        float4 r0, r1;
        r0.x = o[i][0] * inv; r0.y = o[i][1] * inv; r0.z = o[i][2] * inv; r0.w = o[i][3] * inv;
        r1.x = o[i][4] * inv; r1.y = o[i][5] * inv; r1.z = o[i][6] * inv; r1.w = o[i][7] * inv;
        *(float4*)&out[base + tc * 4]      = r0;
        *(float4*)&out[base + 64 + tc * 4] = r1;
    }
}

// =========================== launch sequence ===============================
extern "C" void kernel_launch(void* const* d_in, const int* in_sizes, int n_in,
                              void* d_out, int out_size) {
    const float* hs      = (const float*)d_in[0];
    const float* ln1_g   = (const float*)d_in[1];
    const float* ln1_b   = (const float*)d_in[2];
    const float* w_qkv   = (const float*)d_in[3];
    const float* b_qkv   = (const float*)d_in[4];
    const float* attn_v  = (const float*)d_in[5];
    const float* attn_g  = (const float*)d_in[6];
    const float* attn_b  = (const float*)d_in[7];
    /* d_in[8] = emotion_bias: softmax-invariant, unused */
    const float* ln2_g   = (const float*)d_in[9];
    const float* ln2_b   = (const float*)d_in[10];
    const float* w_fc    = (const float*)d_in[11];
    const float* b_fc    = (const float*)d_in[12];
    const float* mlp_v   = (const float*)d_in[13];
    const float* mlp_g   = (const float*)d_in[14];
    const float* mlp_b   = (const float*)d_in[15];
    float* out = (float*)d_out;

    float *ln, *qkv, *attn, *hid, *fc, *sA, *sM;
    cudaGetSymbolAddress((void**)&ln,   g_ln);
    cudaGetSymbolAddress((void**)&qkv,  g_qkv);
    cudaGetSymbolAddress((void**)&attn, g_attn);
    cudaGetSymbolAddress((void**)&hid,  g_hid);
    cudaGetSymbolAddress((void**)&fc,   g_fc);
    cudaGetSymbolAddress((void**)&sA,   g_sA);
    cudaGetSymbolAddress((void**)&sM,   g_sM);

    const size_t att_smem = (size_t)ATT_SMEM_FLOATS * sizeof(float);
    cudaFuncSetAttribute(attn_kernel,
                         cudaFuncAttributeMaxDynamicSharedMemorySize,
                         (int)att_smem);

    // weight-norm column scales
    colnorm_kernel<<<N_EMBD / 32, 256>>>(attn_v, attn_g, sA, N_EMBD, N_EMBD);
    colnorm_kernel<<<N_INNER / 32, 256>>>(mlp_v, mlp_g, sM, N_EMBD, N_INNER);

    // LN1
    ln_kernel<<<ROWS, 256>>>(hs, ln1_g, ln1_b, ln);

    // QKV: [4096,6144] = ln @ w_qkv^T + b_qkv
    sgemm_nt<false, false, false><<<dim3(QKV_W / 128, ROWS / 128), 256>>>(
        ln, w_qkv, b_qkv, nullptr, nullptr, qkv, ROWS, QKV_W, N_EMBD);

    // attention
    attn_kernel<<<dim3(SEQ / 64, N_HEAD, BATCH), 256, att_smem>>>(qkv, attn);

    // attn proj (weight-norm folded) + residual -> hidden
    sgemm_nt<true, false, true><<<dim3(N_EMBD / 128, ROWS / 128), 256>>>(
        attn, attn_v, attn_b, sA, hs, hid, ROWS, N_EMBD, N_EMBD);

    // LN2
    ln_kernel<<<ROWS, 256>>>(hid, ln2_g, ln2_b, ln);

    // FC + exact GELU: [4096,8192]
    sgemm_nt<false, true, false><<<dim3(N_INNER / 128, ROWS / 128), 256>>>(
        ln, w_fc, b_fc, nullptr, nullptr, fc, ROWS, N_INNER, N_EMBD);

    // MLP proj (weight-norm folded) + residual -> output
    sgemm_nt<true, false, true><<<dim3(N_EMBD / 128, ROWS / 128), 256>>>(
        fc, mlp_v, mlp_b, sM, hid, out, ROWS, N_EMBD, N_INNER);
}